// round 3
// baseline (speedup 1.0000x reference)
#include <cuda_runtime.h>
#include <cuda_bf16.h>

#define NUM_BINS 32
#define NBINS2   (NUM_BINS * NUM_BINS)
#define EPS 1e-5f

// Global scratch histogram (no allocations allowed)
__device__ unsigned int g_hist[NBINS2];

__global__ void zero_hist_kernel() {
    g_hist[threadIdx.x] = 0u;
}

__device__ __forceinline__ int bin_of(float v) {
    // matches jnp.round(v / 255.0 * 31) with IEEE fp32 div/mul and
    // round-to-nearest-even (rintf under default rounding mode)
    return (int)rintf((v / 255.0f) * 31.0f);
}

__global__ void __launch_bounds__(256) hist_kernel(
    const float4* __restrict__ I4,
    const float4* __restrict__ J4,
    int n4)
{
    __shared__ unsigned int sh[NBINS2];
    for (int i = threadIdx.x; i < NBINS2; i += blockDim.x) sh[i] = 0u;
    __syncthreads();

    const int stride = gridDim.x * blockDim.x;
    for (int i = blockIdx.x * blockDim.x + threadIdx.x; i < n4; i += stride) {
        float4 a = I4[i];
        float4 b = J4[i];
        int i0 = bin_of(a.x), j0 = bin_of(b.x);
        int i1 = bin_of(a.y), j1 = bin_of(b.y);
        int i2 = bin_of(a.z), j2 = bin_of(b.z);
        int i3 = bin_of(a.w), j3 = bin_of(b.w);
        atomicAdd(&sh[i0 * NUM_BINS + j0], 1u);
        atomicAdd(&sh[i1 * NUM_BINS + j1], 1u);
        atomicAdd(&sh[i2 * NUM_BINS + j2], 1u);
        atomicAdd(&sh[i3 * NUM_BINS + j3], 1u);
    }
    __syncthreads();

    for (int i = threadIdx.x; i < NBINS2; i += blockDim.x) {
        unsigned int v = sh[i];
        if (v) atomicAdd(&g_hist[i], v);
    }
}

__global__ void __launch_bounds__(1024) mi_kernel(float* __restrict__ out,
                                                  float inv_total)
{
    __shared__ float jp[NBINS2];
    __shared__ float rowp[NUM_BINS];
    __shared__ float colp[NUM_BINS];
    __shared__ float warp_sums[32];

    const int t = threadIdx.x;
    jp[t] = (float)g_hist[t] * inv_total;
    __syncthreads();

    if (t < NUM_BINS) {
        float s = 0.0f;
        #pragma unroll
        for (int c = 0; c < NUM_BINS; c++) s += jp[t * NUM_BINS + c];
        rowp[t] = s;
    } else if (t < 2 * NUM_BINS) {
        int c = t - NUM_BINS;
        float s = 0.0f;
        #pragma unroll
        for (int r = 0; r < NUM_BINS; r++) s += jp[r * NUM_BINS + c];
        colp[c] = s;
    }
    __syncthreads();

    float p  = jp[t];
    float pi = rowp[t >> 5];   // row index = t / 32 = Ib
    float pj = colp[t & 31];   // col index = t % 32 = Jb
    float term = p * (logf(p + EPS) - logf(pi + EPS) - logf(pj + EPS));

    // block reduction: warp shuffle then cross-warp
    #pragma unroll
    for (int off = 16; off > 0; off >>= 1)
        term += __shfl_xor_sync(0xFFFFFFFFu, term, off);
    if ((t & 31) == 0) warp_sums[t >> 5] = term;
    __syncthreads();
    if (t < 32) {
        float s = warp_sums[t];
        #pragma unroll
        for (int off = 16; off > 0; off >>= 1)
            s += __shfl_xor_sync(0xFFFFFFFFu, s, off);
        if (t == 0) {
            float mi = s;
            // sigmoid(-mi) = 1 / (1 + exp(mi))
            out[0] = 1.0f / (1.0f + expf(mi));
        }
    }
}

extern "C" void kernel_launch(void* const* d_in, const int* in_sizes, int n_in,
                              void* d_out, int out_size)
{
    const float* I = (const float*)d_in[0];
    const float* J = (const float*)d_in[1];
    float* out = (float*)d_out;
    const int n  = in_sizes[0];       // 33,554,432 elements
    const int n4 = n / 4;

    zero_hist_kernel<<<1, NBINS2>>>();

    const int threads = 256;
    const int blocks  = 148 * 8;      // 8 CTAs/SM, grid-stride covers all
    hist_kernel<<<blocks, threads>>>((const float4*)I, (const float4*)J, n4);

    mi_kernel<<<1, NBINS2>>>(out, 1.0f / (float)n);
}